// round 2
// baseline (speedup 1.0000x reference)
#include <cuda_runtime.h>
#include <math.h>

// Geometry constants (match reference)
#define NX   256
#define NY   256
#define NZ   32
#define NT   384
#define NANG 180

// Padded, transposed volume: [yp, xp, z] with z innermost.
// Pad ring of 2 zeros on each side (+ safety slack covered by the analysis:
// worst-case indices reach 261 in each axis, still in-bounds).
#define PD     262
#define PADOFF 2.0f
#define ROWF   (PD * NZ)          // floats per padded row = 8384

__device__ float g_volT[PD * PD * NZ];   // 8.79 MB static scratch (fits L2)

// ---------------------------------------------------------------------------
// Kernel 1: zero-pad + transpose [Z,Y,X] -> [Yp,Xp,Z]
// ---------------------------------------------------------------------------
__global__ void pad_transpose_kernel(const float* __restrict__ vol) {
    int idx = blockIdx.x * blockDim.x + threadIdx.x;
    if (idx >= PD * PD * NZ) return;
    int z  = idx & (NZ - 1);
    int xp = (idx >> 5) % PD;
    int yp = (idx >> 5) / PD;
    int x = xp - 2;
    int y = yp - 2;
    float v = 0.0f;
    if (x >= 0 && x < NX && y >= 0 && y < NY)
        v = vol[(z * NY + y) * NX + x];
    g_volT[idx] = v;
}

// ---------------------------------------------------------------------------
// Kernel 2: forward projection.
// One warp per (angle, col); lane = z. Each t-step: 4 coalesced 128B gathers.
// ---------------------------------------------------------------------------
__global__ void __launch_bounds__(256) fp_kernel(const float* __restrict__ phis,
                                                 float* __restrict__ out) {
    const int warp = threadIdx.x >> 5;
    const int lane = threadIdx.x & 31;          // = z
    const int a    = blockIdx.y;
    const int col  = (blockIdx.x << 3) + warp;

    const float phi = phis[a] * 0.017453292519943295f;
    const float c = cosf(phi);
    const float s = sinf(phi);
    const float u = (float)col - 127.5f;

    // Padded fractional coords as a linear function of sample index k:
    //   ixp(k) = Ax + k*c,  iyp(k) = Ay + k*s
    const float Ax = -u * s + 127.5f + PADOFF - 191.5f * c;
    const float Ay =  u * c + 127.5f + PADOFF - 191.5f * s;

    // Valid support (nonzero bilinear weight): padded coord in [1, 258].
    float lo = 0.0f, hi = (float)(NT - 1);
    {
        // X axis
        if (fabsf(c) < 1e-6f) {
            if (Ax < 1.0f || Ax > 258.0f) { lo = 1.0f; hi = 0.0f; }
        } else {
            float t0 = (1.0f   - Ax) / c;
            float t1 = (258.0f - Ax) / c;
            lo = fmaxf(lo, fminf(t0, t1));
            hi = fminf(hi, fmaxf(t0, t1));
        }
        // Y axis
        if (fabsf(s) < 1e-6f) {
            if (Ay < 1.0f || Ay > 258.0f) { lo = 1.0f; hi = 0.0f; }
        } else {
            float t0 = (1.0f   - Ay) / s;
            float t1 = (258.0f - Ay) / s;
            lo = fmaxf(lo, fminf(t0, t1));
            hi = fminf(hi, fmaxf(t0, t1));
        }
    }

    float acc = 0.0f;
    if (hi >= lo) {
        // Expand by 1 sample each side to be robust to fp rounding of bounds.
        // Coordinates then stay within [-1, 260] -> indices within [0, 261].
        int klo = max(0,      (int)floorf(lo) - 1);
        int khi = min(NT - 1, (int)ceilf(hi)  + 1);

        const float* base = g_volT + lane;
        float kf = (float)klo;
        #pragma unroll 4
        for (int k = klo; k <= khi; ++k, kf += 1.0f) {
            float ixp = fmaf(kf, c, Ax);
            float iyp = fmaf(kf, s, Ay);
            int ix0 = (int)ixp;              // trunc == floor (coords >= -1+eps -> >= 0 after trunc)
            int iy0 = (int)iyp;
            float fx = ixp - (float)ix0;
            float fy = iyp - (float)iy0;
            const float* p = base + (iy0 * PD + ix0) * NZ;
            float v00 = __ldg(p);
            float v01 = __ldg(p + NZ);
            float v10 = __ldg(p + ROWF);
            float v11 = __ldg(p + ROWF + NZ);
            float r0 = fmaf(fx, v01 - v00, v00);
            float r1 = fmaf(fx, v11 - v10, v10);
            acc += fmaf(fy, r1 - r0, r0);
        }
    }

    // out[b=0, a, z=lane, col]
    out[(a * NZ + lane) * NX + col] = acc;
}

// ---------------------------------------------------------------------------
extern "C" void kernel_launch(void* const* d_in, const int* in_sizes, int n_in,
                              void* d_out, int out_size) {
    const float* vol  = (const float*)d_in[0];   // [1, 32, 256, 256]
    const float* phis = (const float*)d_in[1];   // [180]
    float* out = (float*)d_out;                  // [1, 180, 32, 256]

    int nAng = in_sizes[1];                      // 180

    {
        int total = PD * PD * NZ;
        pad_transpose_kernel<<<(total + 255) / 256, 256>>>(vol);
    }
    {
        dim3 grid(NX / 8, nAng);                 // 8 warps/block = 8 cols
        fp_kernel<<<grid, 256>>>(phis, out);
    }
}

// round 3
// speedup vs baseline: 1.1717x; 1.1717x over previous
#include <cuda_runtime.h>
#include <math.h>

// Geometry constants (match reference)
#define NX   256
#define NY   256
#define NZ   32
#define NT   384

// Padded, transposed volume: [yp, xp, z] with z innermost.
// Pad ring of 2 zeros on each side; clamped sampling stays within [0, 260].
#define PD     262
#define CELLU  8              // ulonglong2 (16B) units per (y,x) cell (32 floats)
#define ROWU   (PD * CELLU)   // ulonglong2 units per padded row

__device__ __align__(16) float g_volT[PD * PD * NZ];   // 8.79 MB (L2-resident)

// ---------------------------------------------------------------------------
// Kernel 1: zero-pad + transpose [Z,Y,X] -> [Yp,Xp,Z]
// ---------------------------------------------------------------------------
__global__ void pad_transpose_kernel(const float* __restrict__ vol) {
    int idx = blockIdx.x * blockDim.x + threadIdx.x;
    if (idx >= PD * PD * NZ) return;
    int z  = idx & (NZ - 1);
    int xp = (idx >> 5) % PD;
    int yp = (idx >> 5) / PD;
    int x = xp - 2;
    int y = yp - 2;
    float v = 0.0f;
    if (x >= 0 && x < NX && y >= 0 && y < NY)
        v = vol[(z * NY + y) * NX + x];
    g_volT[idx] = v;
}

// packed 2xfp32 fma (sm_103a FFMA2 — only reachable via PTX)
#define FMA2(acc, v, w) \
    asm("fma.rn.f32x2 %0, %1, %2, %0;" : "+l"(acc) : "l"(v), "l"(w))

// ---------------------------------------------------------------------------
// Kernel 2: forward projection.
// Warp = 4 columns x 8 z-groups; each thread covers 4 z via 128-bit loads.
// Weighted-corner accumulation with packed f32x2 FMAs.
// ---------------------------------------------------------------------------
__global__ void __launch_bounds__(256) fp_kernel(const float* __restrict__ phis,
                                                 float* __restrict__ out) {
    const int warp = threadIdx.x >> 5;
    const int lane = threadIdx.x & 31;
    const int csub = lane >> 3;          // column within warp group (0..3)
    const int zi   = lane & 7;           // z-group (4 z per thread)
    const int a    = blockIdx.y;
    const int col  = (((blockIdx.x << 3) + warp) << 2) + csub;

    const float phi = phis[a] * 0.017453292519943295f;
    const float c = cosf(phi);
    const float s = sinf(phi);
    const float u = (float)col - 127.5f;

    // Padded fractional coords: ixp(k) = Ax + k*c, iyp(k) = Ay + k*s
    float Ax = fmaf(-u, s, 129.5f - 191.5f * c);
    float Ay = fmaf( u, c, 129.5f - 191.5f * s);

    // Valid support (nonzero bilinear weight): padded coord in [1, 258].
    float lo = 0.0f, hi = (float)(NT - 1);
    if (fabsf(c) < 1e-6f) {
        if (Ax < 1.0f || Ax > 258.0f) { lo = 1.0f; hi = 0.0f; }
    } else {
        float t0 = (1.0f   - Ax) / c;
        float t1 = (258.0f - Ax) / c;
        lo = fmaxf(lo, fminf(t0, t1));
        hi = fminf(hi, fmaxf(t0, t1));
    }
    if (fabsf(s) < 1e-6f) {
        if (Ay < 1.0f || Ay > 258.0f) { lo = 1.0f; hi = 0.0f; }
    } else {
        float t0 = (1.0f   - Ay) / s;
        float t1 = (258.0f - Ay) / s;
        lo = fmaxf(lo, fminf(t0, t1));
        hi = fminf(hi, fmaxf(t0, t1));
    }

    int klo, khi;
    if (hi >= lo) {
        // Expand by 1 sample each side (robust to fp rounding of bounds).
        klo = max(0,      (int)floorf(lo) - 1);
        khi = min(NT - 1, (int)ceilf(hi)  + 1);
    } else {
        // Geometry guarantees intersection; pure safety fallback.
        klo = 0; khi = -1; Ax = 130.0f; Ay = 130.0f;
    }

    // Warp-union t-range across the 4 columns (all lanes of a column agree).
    int kloW = klo, khiW = khi;
    kloW = min(kloW, __shfl_xor_sync(0xffffffffu, kloW, 8));
    kloW = min(kloW, __shfl_xor_sync(0xffffffffu, kloW, 16));
    khiW = max(khiW, __shfl_xor_sync(0xffffffffu, khiW, 8));
    khiW = max(khiW, __shfl_xor_sync(0xffffffffu, khiW, 16));

    const float kloF = (float)klo, khiF = (float)khi;
    const ulonglong2* __restrict__ base =
        reinterpret_cast<const ulonglong2*>(g_volT) + zi;

    unsigned long long acc0 = 0ull, acc1 = 0ull;   // 4 packed fp32 accumulators

    float kf = (float)kloW;
    #pragma unroll 2
    for (int k = kloW; k <= khiW; ++k, kf += 1.0f) {
        // Clamp k into this column's own valid range; zero weights if outside.
        float kk = fminf(fmaxf(kf, kloF), khiF);
        bool ok  = (kk == kf);
        float ixp = fmaf(kk, c, Ax);
        float iyp = fmaf(kk, s, Ay);
        int ix0 = (int)ixp;                   // coords >= 0 -> trunc == floor
        int iy0 = (int)iyp;
        float fx = ixp - (float)ix0;
        float fy = iyp - (float)iy0;
        float wx0 = 1.0f - fx;
        float wy0 = ok ? (1.0f - fy) : 0.0f;
        float fyz = ok ? fy          : 0.0f;
        float w00 = wx0 * wy0, w01 = fx * wy0;
        float w10 = wx0 * fyz, w11 = fx * fyz;

        unsigned long long w00p, w01p, w10p, w11p;
        asm("mov.b64 %0, {%1, %1};" : "=l"(w00p) : "f"(w00));
        asm("mov.b64 %0, {%1, %1};" : "=l"(w01p) : "f"(w01));
        asm("mov.b64 %0, {%1, %1};" : "=l"(w10p) : "f"(w10));
        asm("mov.b64 %0, {%1, %1};" : "=l"(w11p) : "f"(w11));

        const ulonglong2* p = base + (iy0 * PD + ix0) * CELLU;
        ulonglong2 v00 = p[0];
        ulonglong2 v01 = p[CELLU];
        ulonglong2 v10 = p[ROWU];
        ulonglong2 v11 = p[ROWU + CELLU];

        FMA2(acc0, v00.x, w00p);  FMA2(acc1, v00.y, w00p);
        FMA2(acc0, v01.x, w01p);  FMA2(acc1, v01.y, w01p);
        FMA2(acc0, v10.x, w10p);  FMA2(acc1, v10.y, w10p);
        FMA2(acc0, v11.x, w11p);  FMA2(acc1, v11.y, w11p);
    }

    float r0, r1, r2, r3;
    asm("mov.b64 {%0, %1}, %2;" : "=f"(r0), "=f"(r1) : "l"(acc0));
    asm("mov.b64 {%0, %1}, %2;" : "=f"(r2), "=f"(r3) : "l"(acc1));

    // out[b=0, a, z, col], z = zi*4 .. zi*4+3
    const int z = zi << 2;
    out[((a * NZ) + z    ) * NX + col] = r0;
    out[((a * NZ) + z + 1) * NX + col] = r1;
    out[((a * NZ) + z + 2) * NX + col] = r2;
    out[((a * NZ) + z + 3) * NX + col] = r3;
}

// ---------------------------------------------------------------------------
extern "C" void kernel_launch(void* const* d_in, const int* in_sizes, int n_in,
                              void* d_out, int out_size) {
    const float* vol  = (const float*)d_in[0];   // [1, 32, 256, 256]
    const float* phis = (const float*)d_in[1];   // [180]
    float* out = (float*)d_out;                  // [1, 180, 32, 256]

    int nAng = in_sizes[1];                      // 180

    {
        int total = PD * PD * NZ;
        pad_transpose_kernel<<<(total + 255) / 256, 256>>>(vol);
    }
    {
        dim3 grid(NX / 32, nAng);                // 8 warps/block * 4 cols/warp
        fp_kernel<<<grid, 256>>>(phis, out);
    }
}

// round 5
// speedup vs baseline: 1.2531x; 1.0695x over previous
#include <cuda_runtime.h>
#include <math.h>

// Geometry constants (match reference)
#define NX   256
#define NY   256
#define NZ   32
#define NT   384
#define NANG 180

// Padded, transposed volume: [yp, xp, z] with z innermost.
// Pad ring of 6 zeros per side: warp-union t-ranges overshoot a column's own
// valid range by <= ~5 coordinate units; all such samples land on zeros inside
// the ring, so no per-sample clamping/masking is needed (identical to the
// reference's masked bilinear).
#define PD     268
#define PADI   6
#define CELLU  8              // ulonglong2 (16B) units per (y,x) cell (32 floats)
#define ROWU   (PD * CELLU)   // ulonglong2 units per padded row

__device__ __align__(16) float g_volT[PD * PD * NZ];   // 9.19 MB (L2-resident)

// ---------------------------------------------------------------------------
// Kernel 0: zero output (atomicAdd accumulation needs clean base)
// ---------------------------------------------------------------------------
__global__ void zero_kernel(float* __restrict__ out, int n) {
    int i = blockIdx.x * blockDim.x + threadIdx.x;
    if (i < n) out[i] = 0.0f;
}

// ---------------------------------------------------------------------------
// Kernel 1: zero-pad + transpose [Z,Y,X] -> [Yp,Xp,Z]
// ---------------------------------------------------------------------------
__global__ void pad_transpose_kernel(const float* __restrict__ vol) {
    int idx = blockIdx.x * blockDim.x + threadIdx.x;
    if (idx >= PD * PD * NZ) return;
    int z  = idx & (NZ - 1);
    int xp = (idx >> 5) % PD;
    int yp = (idx >> 5) / PD;
    int x = xp - PADI;
    int y = yp - PADI;
    float v = 0.0f;
    if (x >= 0 && x < NX && y >= 0 && y < NY)
        v = vol[(z * NY + y) * NX + x];
    g_volT[idx] = v;
}

// packed 2xfp32 fma (sm_103a FFMA2 — only reachable via PTX)
#define FMA2(acc, v, w) \
    asm("fma.rn.f32x2 %0, %1, %2, %0;" : "+l"(acc) : "l"(v), "l"(w))

// ---------------------------------------------------------------------------
// Kernel 2: forward projection.
// Warp = 4 columns x 8 z-groups; thread covers 4 z via 128-bit loads.
// blockIdx.z in {0,1} selects the first/second half of the t-range
// (work split for balance + parallelism); halves accumulate via atomicAdd.
// ---------------------------------------------------------------------------
__global__ void __launch_bounds__(128) fp_kernel(const float* __restrict__ phis,
                                                 float* __restrict__ out) {
    const int warp = threadIdx.x >> 5;
    const int lane = threadIdx.x & 31;
    const int csub = lane >> 3;          // column within warp group (0..3)
    const int zi   = lane & 7;           // z-group (4 z per thread)
    const int a    = blockIdx.y;
    const int col  = (((blockIdx.x << 2) + warp) << 2) + csub;

    const float phi = phis[a] * 0.017453292519943295f;
    const float c = cosf(phi);
    const float s = sinf(phi);
    const float u = (float)col - 127.5f;

    // Padded fractional coords: ixp(k) = Ax + k*c, iyp(k) = Ay + k*s
    const float CTR = 127.5f + (float)PADI;               // 133.5
    const float Ax = fmaf(-u, s, CTR - 191.5f * c);
    const float Ay = fmaf( u, c, CTR - 191.5f * s);

    // Support bounds: nonzero bilinear weight <=> padded coord in [PADI-1, PADI+256].
    const float BLO = (float)(PADI - 1);     // 5
    const float BHI = (float)(PADI + 256);   // 262
    float lo = 0.0f, hi = (float)(NT - 1);
    if (fabsf(c) < 1e-6f) {
        if (Ax < BLO || Ax > BHI) { lo = 1.0f; hi = 0.0f; }
    } else {
        float t0 = (BLO - Ax) / c;
        float t1 = (BHI - Ax) / c;
        lo = fmaxf(lo, fminf(t0, t1));
        hi = fminf(hi, fmaxf(t0, t1));
    }
    if (fabsf(s) < 1e-6f) {
        if (Ay < BLO || Ay > BHI) { lo = 1.0f; hi = 0.0f; }
    } else {
        float t0 = (BLO - Ay) / s;
        float t1 = (BHI - Ay) / s;
        lo = fmaxf(lo, fminf(t0, t1));
        hi = fminf(hi, fmaxf(t0, t1));
    }

    // Expand by 1 sample each side (robust to fp rounding of the bounds).
    int klo = max(0,      (int)floorf(lo) - 1);
    int khi = min(NT - 1, (int)ceilf(hi)  + 1);
    khi = max(khi, klo - 1);                 // safety: empty -> length 0

    // Warp-union t-range across the 4 columns (adjacent columns' ranges
    // differ by <= ~4 samples; union stays within the pad ring).
    int kloW = klo, khiW = khi;
    kloW = min(kloW, __shfl_xor_sync(0xffffffffu, kloW, 8));
    kloW = min(kloW, __shfl_xor_sync(0xffffffffu, kloW, 16));
    khiW = max(khiW, __shfl_xor_sync(0xffffffffu, khiW, 8));
    khiW = max(khiW, __shfl_xor_sync(0xffffffffu, khiW, 16));

    // Split the union range into two halves across blockIdx.z.
    {
        int len  = khiW - kloW + 1;
        int kmid = kloW + (len >> 1);
        if (blockIdx.z == 0) khiW = kmid - 1;
        else                 kloW = kmid;
    }

    const ulonglong2* __restrict__ base =
        reinterpret_cast<const ulonglong2*>(g_volT) + zi;

    unsigned long long acc0 = 0ull, acc1 = 0ull;   // 4 packed fp32 accumulators

    float kf = (float)kloW;
    #pragma unroll 2
    for (int k = kloW; k <= khiW; ++k, kf += 1.0f) {
        float ixp = fmaf(kf, c, Ax);
        float iyp = fmaf(kf, s, Ay);
        int ix0 = (int)ixp;                   // coords >= 1 -> trunc == floor
        int iy0 = (int)iyp;
        float fx = ixp - (float)ix0;
        float fy = iyp - (float)iy0;
        float wx0 = 1.0f - fx;
        float wy0 = 1.0f - fy;
        float w00 = wx0 * wy0, w01 = fx * wy0;
        float w10 = wx0 * fy,  w11 = fx * fy;

        unsigned long long w00p, w01p, w10p, w11p;
        asm("mov.b64 %0, {%1, %1};" : "=l"(w00p) : "f"(w00));
        asm("mov.b64 %0, {%1, %1};" : "=l"(w01p) : "f"(w01));
        asm("mov.b64 %0, {%1, %1};" : "=l"(w10p) : "f"(w10));
        asm("mov.b64 %0, {%1, %1};" : "=l"(w11p) : "f"(w11));

        const ulonglong2* p = base + (iy0 * PD + ix0) * CELLU;
        ulonglong2 v00 = p[0];
        ulonglong2 v01 = p[CELLU];
        ulonglong2 v10 = p[ROWU];
        ulonglong2 v11 = p[ROWU + CELLU];

        FMA2(acc0, v00.x, w00p);  FMA2(acc1, v00.y, w00p);
        FMA2(acc0, v01.x, w01p);  FMA2(acc1, v01.y, w01p);
        FMA2(acc0, v10.x, w10p);  FMA2(acc1, v10.y, w10p);
        FMA2(acc0, v11.x, w11p);  FMA2(acc1, v11.y, w11p);
    }

    float r0, r1, r2, r3;
    asm("mov.b64 {%0, %1}, %2;" : "=f"(r0), "=f"(r1) : "l"(acc0));
    asm("mov.b64 {%0, %1}, %2;" : "=f"(r2), "=f"(r3) : "l"(acc1));

    // out[b=0, a, z, col], z = zi*4 .. zi*4+3 ; two t-halves accumulate.
    const int z = zi << 2;
    float* o = out + (a * NZ + z) * NX + col;
    atomicAdd(o,            r0);
    atomicAdd(o + NX,       r1);
    atomicAdd(o + 2 * NX,   r2);
    atomicAdd(o + 3 * NX,   r3);
}

// ---------------------------------------------------------------------------
extern "C" void kernel_launch(void* const* d_in, const int* in_sizes, int n_in,
                              void* d_out, int out_size) {
    const float* vol  = (const float*)d_in[0];   // [1, 32, 256, 256]
    const float* phis = (const float*)d_in[1];   // [180]
    float* out = (float*)d_out;                  // [1, 180, 32, 256]

    int nAng = in_sizes[1];                      // 180

    zero_kernel<<<(out_size + 255) / 256, 256>>>(out, out_size);
    {
        int total = PD * PD * NZ;
        pad_transpose_kernel<<<(total + 255) / 256, 256>>>(vol);
    }
    {
        dim3 grid(NX / 16, nAng, 2);             // 4 warps/block * 4 cols/warp
        fp_kernel<<<grid, 128>>>(phis, out);
    }
}